// round 7
// baseline (speedup 1.0000x reference)
#include <cuda_runtime.h>
#include <cuda_bf16.h>
#include <math.h>

#define NN 64
#define BATCH 4096
#define TPB 256
#define NBLK (BATCH / (TPB / 32))   // 512 blocks: one warp per batch
#define EPS_PEN 0.1f
// penalty == 0 certified iff xmin >= logit(EPS/NN) = -6.459905...; use tighter -6.4599
#define XMIN_THRESH -6.4599f
#define PEN_SCALE 1099511627776.0   // 2^40 fixed-point, order-independent accumulation

__device__ unsigned long long g_acc;            // fixed-point penalty accumulator
__device__ unsigned int       g_count;          // completion counter
__device__ unsigned int       g_nfail;          // # batches needing eigensolve
__device__ int                g_fail[BATCH];    // their indices

// Block-wide (256-thread, 8-warp) sum reduction. All 256 threads must call.
__device__ __forceinline__ float block_reduce256(float v, volatile float* red) {
    #pragma unroll
    for (int o = 16; o > 0; o >>= 1)
        v += __shfl_xor_sync(0xffffffffu, v, o);
    if ((threadIdx.x & 31) == 0) red[threadIdx.x >> 5] = v;
    __syncthreads();
    float r = ((red[0] + red[1]) + (red[2] + red[3]))
            + ((red[4] + red[5]) + (red[6] + red[7]));
    __syncthreads();
    return r;
}

// Full eigensolve for one batch. ALL 256 threads enter (threads >= 64 idle at barriers).
__device__ void slow_path_eig(const float* __restrict__ src, int tid,
                              float M[NN][NN + 1], float* u, float* w,
                              float* dd, float* ee2, volatile float* red) {
    // ---- Load + sigmoid ----
    for (int idx = tid; idx < NN * NN; idx += TPB) {
        float x = src[idx];
        float s = 1.0f / (1.0f + expf(-x));
        M[idx >> 6][idx & 63] = s;
    }
    __syncthreads();

    float deg = 0.0f, aii = 0.0f;
    if (tid < NN) {
        #pragma unroll 8
        for (int j = 0; j < NN; j++) deg += M[tid][j];
        aii = M[tid][tid];
    }
    __syncthreads();

    if (tid < NN) {
        for (int j = tid + 1; j < NN; j++) {
            float v = -0.5f * (M[tid][j] + M[j][tid]);
            M[tid][j] = v;
            M[j][tid] = v;
        }
        M[tid][tid] = deg - aii;
    }
    __syncthreads();

    // ---- Householder tridiagonalization ----
    for (int k = 0; k < NN - 2; k++) {
        float xi = (tid > k && tid < NN) ? M[tid][k] : 0.0f;
        float sigma = block_reduce256(xi * xi, red);

        float x1 = M[k + 1][k];
        float nrm = sqrtf(sigma);
        float alpha = (x1 >= 0.0f) ? -nrm : nrm;
        if (tid == 0) ee2[k] = sigma;

        float vnorm2 = 2.0f * (sigma - x1 * alpha);
        float invv = 2.0f / fmaxf(vnorm2, 1e-30f);

        if (tid < NN) {
            float vi = (tid > k) ? M[tid][k] : 0.0f;
            if (tid == k + 1) vi -= alpha;
            u[tid] = vi;
        }
        __syncthreads();

        float pi = 0.0f;
        if (tid > k && tid < NN) {
            #pragma unroll 4
            for (int j = k + 1; j < NN; j++) pi += M[tid][j] * u[j];
            pi *= invv;
        }

        float uv = (tid < NN) ? u[tid] : 0.0f;
        float s = block_reduce256(uv * pi, red);
        float K = 0.5f * invv * s;
        if (tid < NN) w[tid] = pi - K * uv;
        __syncthreads();

        if (tid > k && tid < NN) {
            float vloc = u[tid];
            float wloc = w[tid];
            #pragma unroll 4
            for (int j = k + 1; j < NN; j++)
                M[tid][j] -= vloc * w[j] + wloc * u[j];
        }
        __syncthreads();
    }

    if (tid < NN) dd[tid] = M[tid][tid];
    if (tid == 0) {
        float t = M[NN - 1][NN - 2];
        ee2[NN - 2] = t * t;
        ee2[NN - 1] = 0.0f;
    }
    __syncthreads();

    // ---- Warp-0 multisection bisection for lambda_2 ----
    if (tid < 32) {
        float gl = 1e30f, gu = -1e30f;
        for (int i = tid; i < NN; i += 32) {
            float ei  = sqrtf(ee2[i]);
            float eim = (i > 0) ? sqrtf(ee2[i - 1]) : 0.0f;
            float r = ei + eim;
            gl = fminf(gl, dd[i] - r);
            gu = fmaxf(gu, dd[i] + r);
        }
        #pragma unroll
        for (int o = 16; o > 0; o >>= 1) {
            gl = fminf(gl, __shfl_xor_sync(0xffffffffu, gl, o));
            gu = fmaxf(gu, __shfl_xor_sync(0xffffffffu, gu, o));
        }

        float lo = gl, hi = gu;
        #pragma unroll 1
        for (int round = 0; round < 6; round++) {
            float stepw = (hi - lo) * (1.0f / 33.0f);
            float x = lo + stepw * (float)(tid + 1);
            float q = dd[0] - x;
            int c = (q < 0.0f);
            #pragma unroll 1
            for (int i = 1; i < NN; i++) {
                float den = q;
                if (fabsf(den) < 1e-30f) den = -1e-30f;
                q = dd[i] - x - ee2[i - 1] / den;
                c += (q < 0.0f);
            }
            unsigned bal = __ballot_sync(0xffffffffu, c >= 2);
            if (bal == 0u) {
                lo += stepw * 32.0f;
            } else {
                int t = __ffs(bal) - 1;
                hi = lo + stepw * (float)(t + 1);
                lo += stepw * (float)t;
            }
        }
        float lambda2 = 0.5f * (lo + hi);
        if (tid == 0) {
            float pen = fmaxf(0.0f, EPS_PEN - lambda2);
            unsigned long long q = (unsigned long long)((double)pen * PEN_SCALE);
            atomicAdd(&g_acc, q);   // order-independent => deterministic
        }
    }
    __syncthreads();
}

__global__ void __launch_bounds__(TPB, 8)
spectral_kernel(const float* __restrict__ logits, float* __restrict__ out) {
    __shared__ float M[NN][NN + 1];
    __shared__ float u[NN];
    __shared__ float w[NN];
    __shared__ float dd[NN];
    __shared__ float ee2[NN];
    __shared__ float red[8];
    __shared__ int   s_last;

    const int tid  = threadIdx.x;
    const int lane = tid & 31;
    const int b    = blockIdx.x * (TPB / 32) + (tid >> 5);   // one batch per warp

    // ======== FAST PATH: warp-local streaming min, zero barriers ========
    const float4* src4 = (const float4*)(logits + (size_t)b * NN * NN);
    float m = 1e30f;
    #pragma unroll
    for (int i = 0; i < 8; i++) {
        float4 v = src4[lane + 32 * i];
        m = fminf(m, fminf(fminf(v.x, v.y), fminf(v.z, v.w)));
    }
    #pragma unroll
    for (int o = 16; o > 0; o >>= 1)
        m = fminf(m, __shfl_xor_sync(0xffffffffu, m, o));

    // certified: lambda_2 >= NN*sigmoid(m) >= EPS  <=>  m >= THRESH  => penalty 0
    if (m < XMIN_THRESH) {
        if (lane == 0) {
            unsigned int slot = atomicAdd(&g_nfail, 1u);
            g_fail[slot] = b;
        }
    }

    // ======== last-block-done: drain fail list + finalize ========
    if (tid == 0) {
        __threadfence();
        unsigned int old = atomicAdd(&g_count, 1u);
        s_last = (old == NBLK - 1u) ? 1 : 0;
    }
    __syncthreads();

    if (s_last) {
        __threadfence();
        unsigned int nf = *((volatile unsigned int*)&g_nfail);
        for (unsigned int i = 0; i < nf; i++) {
            int fb = ((volatile int*)g_fail)[i];
            slow_path_eig(logits + (size_t)fb * NN * NN, tid, M, u, w, dd, ee2, red);
        }
        if (tid == 0) {
            unsigned long long a = g_acc;
            out[0] = (float)((double)a * (1.0 / PEN_SCALE) * (1.0 / (double)BATCH));
            g_acc = 0ull;                // reset for next graph replay
            g_nfail = 0u;
            __threadfence();
            g_count = 0u;
        }
    }
}

extern "C" void kernel_launch(void* const* d_in, const int* in_sizes, int n_in,
                              void* d_out, int out_size) {
    const float* logits = (const float*)d_in[0];   // [4096, 64, 64] float32
    // d_in[1] = node_types (int64) — unused by the reference computation
    float* out = (float*)d_out;

    spectral_kernel<<<NBLK, TPB>>>(logits, out);
}

// round 8
// speedup vs baseline: 1.0332x; 1.0332x over previous
#include <cuda_runtime.h>
#include <cuda_bf16.h>
#include <math.h>

#define NN 64
#define BATCH 4096
#define TPB 256
#define NBLK (BATCH / (TPB / 32))   // 512 blocks: one warp per batch
#define EPS_PEN 0.1f
// penalty == 0 certified iff xmin >= logit(EPS/NN) = -6.459905...; use tighter -6.4599
#define XMIN_THRESH -6.4599f
#define PEN_SCALE 1099511627776.0   // 2^40 fixed-point, order-independent accumulation

__device__ unsigned long long g_acc;            // fixed-point penalty accumulator
__device__ unsigned int       g_count;          // completion counter
__device__ unsigned int       g_nfail;          // # batches needing eigensolve
__device__ int                g_fail[BATCH];    // their indices

// Block-wide (256-thread, 8-warp) sum reduction. All 256 threads must call.
__device__ __forceinline__ float block_reduce256(float v, volatile float* red) {
    #pragma unroll
    for (int o = 16; o > 0; o >>= 1)
        v += __shfl_xor_sync(0xffffffffu, v, o);
    if ((threadIdx.x & 31) == 0) red[threadIdx.x >> 5] = v;
    __syncthreads();
    float r = ((red[0] + red[1]) + (red[2] + red[3]))
            + ((red[4] + red[5]) + (red[6] + red[7]));
    __syncthreads();
    return r;
}

// Full eigensolve for one batch. ALL 256 threads enter (threads >= 64 idle at barriers).
__device__ void slow_path_eig(const float* __restrict__ src, int tid,
                              float M[NN][NN + 1], float* u, float* w,
                              float* dd, float* ee2, volatile float* red) {
    // ---- Load + sigmoid ----
    for (int idx = tid; idx < NN * NN; idx += TPB) {
        float x = src[idx];
        float s = 1.0f / (1.0f + expf(-x));
        M[idx >> 6][idx & 63] = s;
    }
    __syncthreads();

    float deg = 0.0f, aii = 0.0f;
    if (tid < NN) {
        #pragma unroll 8
        for (int j = 0; j < NN; j++) deg += M[tid][j];
        aii = M[tid][tid];
    }
    __syncthreads();

    if (tid < NN) {
        for (int j = tid + 1; j < NN; j++) {
            float v = -0.5f * (M[tid][j] + M[j][tid]);
            M[tid][j] = v;
            M[j][tid] = v;
        }
        M[tid][tid] = deg - aii;
    }
    __syncthreads();

    // ---- Householder tridiagonalization ----
    for (int k = 0; k < NN - 2; k++) {
        float xi = (tid > k && tid < NN) ? M[tid][k] : 0.0f;
        float sigma = block_reduce256(xi * xi, red);

        float x1 = M[k + 1][k];
        float nrm = sqrtf(sigma);
        float alpha = (x1 >= 0.0f) ? -nrm : nrm;
        if (tid == 0) ee2[k] = sigma;

        float vnorm2 = 2.0f * (sigma - x1 * alpha);
        float invv = 2.0f / fmaxf(vnorm2, 1e-30f);

        if (tid < NN) {
            float vi = (tid > k) ? M[tid][k] : 0.0f;
            if (tid == k + 1) vi -= alpha;
            u[tid] = vi;
        }
        __syncthreads();

        float pi = 0.0f;
        if (tid > k && tid < NN) {
            #pragma unroll 4
            for (int j = k + 1; j < NN; j++) pi += M[tid][j] * u[j];
            pi *= invv;
        }

        float uv = (tid < NN) ? u[tid] : 0.0f;
        float s = block_reduce256(uv * pi, red);
        float K = 0.5f * invv * s;
        if (tid < NN) w[tid] = pi - K * uv;
        __syncthreads();

        if (tid > k && tid < NN) {
            float vloc = u[tid];
            float wloc = w[tid];
            #pragma unroll 4
            for (int j = k + 1; j < NN; j++)
                M[tid][j] -= vloc * w[j] + wloc * u[j];
        }
        __syncthreads();
    }

    if (tid < NN) dd[tid] = M[tid][tid];
    if (tid == 0) {
        float t = M[NN - 1][NN - 2];
        ee2[NN - 2] = t * t;
        ee2[NN - 1] = 0.0f;
    }
    __syncthreads();

    // ---- Warp-0 multisection bisection for lambda_2 ----
    if (tid < 32) {
        float gl = 1e30f, gu = -1e30f;
        for (int i = tid; i < NN; i += 32) {
            float ei  = sqrtf(ee2[i]);
            float eim = (i > 0) ? sqrtf(ee2[i - 1]) : 0.0f;
            float r = ei + eim;
            gl = fminf(gl, dd[i] - r);
            gu = fmaxf(gu, dd[i] + r);
        }
        #pragma unroll
        for (int o = 16; o > 0; o >>= 1) {
            gl = fminf(gl, __shfl_xor_sync(0xffffffffu, gl, o));
            gu = fmaxf(gu, __shfl_xor_sync(0xffffffffu, gu, o));
        }

        float lo = gl, hi = gu;
        #pragma unroll 1
        for (int round = 0; round < 6; round++) {
            float stepw = (hi - lo) * (1.0f / 33.0f);
            float x = lo + stepw * (float)(tid + 1);
            float q = dd[0] - x;
            int c = (q < 0.0f);
            #pragma unroll 1
            for (int i = 1; i < NN; i++) {
                float den = q;
                if (fabsf(den) < 1e-30f) den = -1e-30f;
                q = dd[i] - x - ee2[i - 1] / den;
                c += (q < 0.0f);
            }
            unsigned bal = __ballot_sync(0xffffffffu, c >= 2);
            if (bal == 0u) {
                lo += stepw * 32.0f;
            } else {
                int t = __ffs(bal) - 1;
                hi = lo + stepw * (float)(t + 1);
                lo += stepw * (float)t;
            }
        }
        float lambda2 = 0.5f * (lo + hi);
        if (tid == 0) {
            float pen = fmaxf(0.0f, EPS_PEN - lambda2);
            unsigned long long q = (unsigned long long)((double)pen * PEN_SCALE);
            atomicAdd(&g_acc, q);   // order-independent => deterministic
        }
    }
    __syncthreads();
}

__global__ void __launch_bounds__(TPB, 8)
spectral_kernel(const float* __restrict__ logits, float* __restrict__ out) {
    __shared__ float M[NN][NN + 1];
    __shared__ float u[NN];
    __shared__ float w[NN];
    __shared__ float dd[NN];
    __shared__ float ee2[NN];
    __shared__ float red[8];
    __shared__ int   s_last;

    const int tid  = threadIdx.x;
    const int lane = tid & 31;
    const int b    = blockIdx.x * (TPB / 32) + (tid >> 5);   // one batch per warp

    // ======== FAST PATH: warp-local streaming min, zero barriers ========
    const float4* src4 = (const float4*)(logits + (size_t)b * NN * NN);
    float m = 1e30f;
    #pragma unroll
    for (int i = 0; i < 8; i++) {
        float4 v = src4[lane + 32 * i];
        m = fminf(m, fminf(fminf(v.x, v.y), fminf(v.z, v.w)));
    }
    #pragma unroll
    for (int o = 16; o > 0; o >>= 1)
        m = fminf(m, __shfl_xor_sync(0xffffffffu, m, o));

    // certified: lambda_2 >= NN*sigmoid(m) >= EPS  <=>  m >= THRESH  => penalty 0
    if (m < XMIN_THRESH) {
        if (lane == 0) {
            unsigned int slot = atomicAdd(&g_nfail, 1u);
            g_fail[slot] = b;
        }
    }

    // ======== last-block-done: drain fail list + finalize ========
    if (tid == 0) {
        __threadfence();
        unsigned int old = atomicAdd(&g_count, 1u);
        s_last = (old == NBLK - 1u) ? 1 : 0;
    }
    __syncthreads();

    if (s_last) {
        __threadfence();
        unsigned int nf = *((volatile unsigned int*)&g_nfail);
        for (unsigned int i = 0; i < nf; i++) {
            int fb = ((volatile int*)g_fail)[i];
            slow_path_eig(logits + (size_t)fb * NN * NN, tid, M, u, w, dd, ee2, red);
        }
        if (tid == 0) {
            unsigned long long a = g_acc;
            out[0] = (float)((double)a * (1.0 / PEN_SCALE) * (1.0 / (double)BATCH));
            g_acc = 0ull;                // reset for next graph replay
            g_nfail = 0u;
            __threadfence();
            g_count = 0u;
        }
    }
}

extern "C" void kernel_launch(void* const* d_in, const int* in_sizes, int n_in,
                              void* d_out, int out_size) {
    const float* logits = (const float*)d_in[0];   // [4096, 64, 64] float32
    // d_in[1] = node_types (int64) — unused by the reference computation
    float* out = (float*)d_out;

    spectral_kernel<<<NBLK, TPB>>>(logits, out);
}